// round 1
// baseline (speedup 1.0000x reference)
#include <cuda_runtime.h>
#include <cstdint>

// 2x nearest-neighbor upsample: [B*C, 256, 256] f32 -> [B*C, 512, 512] f32.
// One thread per input float4 (4 consecutive w elements).
// 1x LDG.128, 4x STG.128 per thread; all accesses coalesced.

constexpr int H = 256;
constexpr int W = 256;
constexpr int W4 = W / 4;          // float4s per input row = 64
constexpr int OW = W * 2;          // 512

__global__ void upsample2x_kernel(const float4* __restrict__ in,
                                  float4* __restrict__ out,
                                  int total4) {
    int i = blockIdx.x * blockDim.x + threadIdx.x;
    if (i >= total4) return;

    // decompose: i = ((bc * H) + h) * W4 + w4
    int w4 = i % W4;
    int t  = i / W4;
    int h  = t % H;
    int bc = t / H;

    float4 v = in[i];

    float4 lo = make_float4(v.x, v.x, v.y, v.y);
    float4 hi = make_float4(v.z, v.z, v.w, v.w);

    // output: row stride OW floats = OW/4 float4s = 128
    // out element col = 2 * (4*w4) = 8*w4 -> float4 index = 2*w4
    long obase = ((long)bc * (2 * H) + 2 * h) * (OW / 4) + 2 * w4;

    out[obase]                = lo;
    out[obase + 1]            = hi;
    out[obase + (OW / 4)]     = lo;
    out[obase + (OW / 4) + 1] = hi;
}

extern "C" void kernel_launch(void* const* d_in, const int* in_sizes, int n_in,
                              void* d_out, int out_size) {
    const float4* in = (const float4*)d_in[0];
    float4* out = (float4*)d_out;
    int total4 = in_sizes[0] / 4;   // 16 * 64 * 256 * 256 / 4 = 16,777,216

    int block = 256;
    int grid = (total4 + block - 1) / block;
    upsample2x_kernel<<<grid, block>>>(in, out, total4);
}

// round 6
// speedup vs baseline: 1.0988x; 1.0988x over previous
#include <cuda_runtime.h>
#include <cstdint>

// 2x nearest-neighbor upsample: [B*C, 256, 256] f32 -> [B*C, 512, 512] f32.
// One thread per OUTPUT float4: reads one input float2 (contiguous across
// warp -> 2 wavefronts), writes one output float4 (contiguous -> 4 wavefronts).
// Both output rows derived from an input row are produced inside the same CTA,
// so the second read of each input row hits L1.

constexpr int H  = 256;
constexpr int W  = 256;
constexpr int OH = 2 * H;            // 512
constexpr int OW = 2 * W;            // 512
constexpr int OW4 = OW / 4;          // 128 output float4s per output row
constexpr int IW2 = W / 2;           // 128 input float2s per input row

__global__ void upsample2x_kernel(const float2* __restrict__ in,
                                  float4* __restrict__ out,
                                  int total4) {
    int j = blockIdx.x * blockDim.x + threadIdx.x;
    if (j >= total4) return;

    // j = ((bc * OH) + oh) * OW4 + ow4   (all powers of two)
    int ow4 = j & (OW4 - 1);
    int t   = j >> 7;                // / OW4
    int oh  = t & (OH - 1);
    int bc  = t >> 9;                // / OH

    int h = oh >> 1;
    // output float4 #ow4 covers output cols [4*ow4, 4*ow4+3]
    //   -> input cols [2*ow4, 2*ow4+1] -> input float2 #ow4
    float2 v = in[((bc << 8) + h) * IW2 + ow4];

    out[j] = make_float4(v.x, v.x, v.y, v.y);
}

extern "C" void kernel_launch(void* const* d_in, const int* in_sizes, int n_in,
                              void* d_out, int out_size) {
    const float2* in = (const float2*)d_in[0];
    float4* out = (float4*)d_out;
    int total4 = out_size / 4;       // 16*64*512*512/4 = 67,108,864

    int block = 256;
    int grid = (total4 + block - 1) / block;
    upsample2x_kernel<<<grid, block>>>(in, out, total4);
}

// round 9
// speedup vs baseline: 1.2646x; 1.1508x over previous
#include <cuda_runtime.h>
#include <cstdint>

// 2x nearest-neighbor upsample: [B*C, 256, 256] f32 -> [B*C, 512, 512] f32.
// One thread per (bc, h, ow4 in [0,64)):
//   - loads input float2 at ow4 and ow4+64 (both coalesced, front-batched)
//   - writes 4 coalesced float4 stores: cols {ow4, ow4+64} x rows {2h, 2h+1}
// 2 independent LDG.64 + 4 independent STG.128 per thread.

constexpr int H   = 256;
constexpr int IW2 = 128;     // input float2s per row
constexpr int OW4 = 128;     // output float4s per row

__global__ void upsample2x_kernel(const float2* __restrict__ in,
                                  float4* __restrict__ out,
                                  int total) {
    int i = blockIdx.x * blockDim.x + threadIdx.x;
    if (i >= total) return;

    // i = ((bc * H) + h) * 64 + ow4a,  ow4a in [0,64)
    int ow4a = i & 63;
    int t    = i >> 6;
    int h    = t & (H - 1);
    int bc   = t >> 8;

    long ibase = ((long)(bc << 8) + h) * IW2 + ow4a;
    float2 va = in[ibase];
    float2 vb = in[ibase + 64];

    float4 fa = make_float4(va.x, va.x, va.y, va.y);
    float4 fb = make_float4(vb.x, vb.x, vb.y, vb.y);

    long obase = ((long)(bc << 9) + (h << 1)) * OW4 + ow4a;

    out[obase]             = fa;
    out[obase + 64]        = fb;
    out[obase + OW4]       = fa;
    out[obase + OW4 + 64]  = fb;
}

extern "C" void kernel_launch(void* const* d_in, const int* in_sizes, int n_in,
                              void* d_out, int out_size) {
    const float2* in = (const float2*)d_in[0];
    float4* out = (float4*)d_out;
    // one thread per 4 input floats: 67,108,864 / 4 = 16,777,216
    int total = in_sizes[0] >> 2;

    int block = 256;
    int grid = (total + block - 1) / block;
    upsample2x_kernel<<<grid, block>>>(in, out, total);
}